// round 5
// baseline (speedup 1.0000x reference)
#include <cuda_runtime.h>
#include <cuda_bf16.h>
#include <cstdint>

#define TPB 128

// ---------------- smem layout (bytes) ----------------
static constexpr int S_FRAG = 0;        // 112 frag-entries * 32 lanes * 8B = 28672
static constexpr int S_T0   = 28672;    // A tiles: 128 rows * 80B = 10240 each
static constexpr int S_T1   = 38912;
static constexpr int S_T2   = 49152;
static constexpr int S_T3   = 59392;
static constexpr int S_C    = 69632;    // C buffer: 128 rows * 36 fp32 = 18432
static constexpr int SMEM_TOTAL = 88064;

// frag index bases (each idx = one (ntile,kstep) B fragment set, 32 lanes x u64)
static constexpr int FQ = 0, FK = 8, FVH = 16, FVL = 24, FW1 = 32, FW2 = 64, FWO = 96;

extern __shared__ char smc[];

// ---------------- helpers ----------------
__device__ __forceinline__ uint32_t smem_to_u32(const void* p) {
    uint32_t a;
    asm("{ .reg .u64 t; cvta.to.shared.u64 t, %1; cvt.u32.u64 %0, t; }"
        : "=r"(a) : "l"(p));
    return a;
}
__device__ __forceinline__ uint32_t pbf2(float a, float b) {
    __nv_bfloat162 t = __floats2bfloat162_rn(a, b);
    return *reinterpret_cast<uint32_t*>(&t);
}
__device__ __forceinline__ float bfhi(float v) {
    return __bfloat162float(__float2bfloat16(v));
}
__device__ __forceinline__ void ldmA(uint32_t* a, uint32_t addr) {
    asm volatile("ldmatrix.sync.aligned.m8n8.x4.shared.b16 {%0,%1,%2,%3}, [%4];"
                 : "=r"(a[0]), "=r"(a[1]), "=r"(a[2]), "=r"(a[3]) : "r"(addr));
}
__device__ __forceinline__ void mma16816(float* c, const uint32_t* a,
                                         uint32_t b0, uint32_t b1) {
    asm volatile(
        "mma.sync.aligned.m16n8k16.row.col.f32.bf16.bf16.f32 "
        "{%0,%1,%2,%3}, {%4,%5,%6,%7}, {%8,%9}, {%0,%1,%2,%3};\n"
        : "+f"(c[0]), "+f"(c[1]), "+f"(c[2]), "+f"(c[3])
        : "r"(a[0]), "r"(a[1]), "r"(a[2]), "r"(a[3]), "r"(b0), "r"(b1));
}
__device__ __forceinline__ void ldfrag(uint32_t& b0, uint32_t& b1, int idx, int lane8) {
    unsigned long long f =
        *(const unsigned long long*)(smc + S_FRAG + idx * 256 + lane8);
    b0 = (uint32_t)f;
    b1 = (uint32_t)(f >> 32);
}
// B fragment for mma.m16n8k16 col-major B: lane holds (k0,n),(k0+1,n) | (k0+8,n),(k0+9,n)
__device__ __forceinline__ unsigned long long make_frag(
    const float* W, int ldn, int nmax, int k0, int n, bool lo) {
    float e[4];
#pragma unroll
    for (int j = 0; j < 4; j++) {
        int k = k0 + (j >> 1) * 8 + (j & 1);
        float v = (n < nmax) ? W[k * ldn + n] : 0.0f;
        e[j] = lo ? (v - bfhi(v)) : v;
    }
    uint32_t b0 = pbf2(e[0], e[1]);
    uint32_t b1 = pbf2(e[2], e[3]);
    return (unsigned long long)b0 | ((unsigned long long)b1 << 32);
}
// stage one fp32 row (32 vals) as hi+lo bf16 A-tile rows (80B stride)
__device__ __forceinline__ void stage_hilo(const float* v, int tid,
                                           int off_hi, int off_lo) {
#pragma unroll
    for (int c = 0; c < 4; c++) {
        uint32_t hw[4], lw[4];
#pragma unroll
        for (int j = 0; j < 4; j++) {
            float v0 = v[8 * c + 2 * j], v1 = v[8 * c + 2 * j + 1];
            hw[j] = pbf2(v0, v1);
            lw[j] = pbf2(v0 - bfhi(v0), v1 - bfhi(v1));
        }
        *(uint4*)(smc + off_hi + tid * 80 + c * 16) = make_uint4(hw[0], hw[1], hw[2], hw[3]);
        *(uint4*)(smc + off_lo + tid * 80 + c * 16) = make_uint4(lw[0], lw[1], lw[2], lw[3]);
    }
}
__device__ __forceinline__ void read_row32(float* d, int tid) {
#pragma unroll
    for (int c = 0; c < 8; c++) {
        float4 t = *(const float4*)(smc + S_C + tid * 144 + c * 16);
        d[4 * c] = t.x; d[4 * c + 1] = t.y; d[4 * c + 2] = t.z; d[4 * c + 3] = t.w;
    }
}
__device__ __forceinline__ void layernorm32(float* v) {
    float s1 = 0.0f, s2 = 0.0f;
#pragma unroll
    for (int e = 0; e < 32; e++) { s1 += v[e]; s2 += v[e] * v[e]; }
    float mu  = s1 * (1.0f / 32.0f);
    float var = s2 * (1.0f / 32.0f) - mu * mu;
    float rs  = rsqrtf(var + 1e-5f);
#pragma unroll
    for (int e = 0; e < 32; e++) v[e] = (v[e] - mu) * rs;
}

__global__ void __launch_bounds__(TPB, 2)
mt_mma_kernel(const int* __restrict__ tokens,
              const float* __restrict__ g_tokE, const float* __restrict__ g_posE,
              const float* __restrict__ g_Wq,  const float* __restrict__ g_Wk,
              const float* __restrict__ g_Wv,  const float* __restrict__ g_W1,
              const float* __restrict__ g_W2,  const float* __restrict__ g_Wout,
              float* __restrict__ g_out)
{
    const uint32_t sb = smem_to_u32(smc);
    const int tid  = threadIdx.x;
    const int wid  = tid >> 5;
    const int lane = tid & 31;
    const int g    = lane >> 2;
    const int tg   = lane & 3;
    const int lane8 = lane * 8;

    // ---- B fragment precompute (lane-exact mma layout) ----
    for (int i = tid; i < 112 * 32; i += TPB) {
        int fl = i & 31, idx = i >> 5;
        int fg = fl >> 2, ftg = fl & 3;
        unsigned long long fr;
        if (idx < 32) {
            int mat = idx >> 3, nt = (idx >> 1) & 3, kk = idx & 1;
            const float* W = (mat == 0) ? g_Wq : (mat == 1) ? g_Wk : g_Wv;
            fr = make_frag(W, 32, 32, kk * 16 + 2 * ftg, nt * 8 + fg, mat == 3);
        } else if (idx < 64) {
            int j = idx - 32, half = j >> 4, nt = (j >> 2) & 3, kk = (j >> 1) & 1, lo = j & 1;
            fr = make_frag(g_W1, 64, 64, kk * 16 + 2 * ftg, half * 32 + nt * 8 + fg, lo != 0);
        } else if (idx < 96) {
            int j = idx - 64, nt = j >> 3, kk = (j >> 1) & 3, lo = j & 1;
            fr = make_frag(g_W2, 32, 32, kk * 16 + 2 * ftg, nt * 8 + fg, lo != 0);
        } else {
            int j = idx - 96, nt = j >> 2, kk = (j >> 1) & 1, lo = j & 1;
            fr = make_frag(g_Wout, 27, 27, kk * 16 + 2 * ftg, nt * 8 + fg, lo != 0);
        }
        *(unsigned long long*)(smc + S_FRAG + i * 8) = fr;
    }

    // ---- x = tok_emb[tok] + pos_emb[t] (fp32 regs); stage hi/lo A tiles ----
    const int row = blockIdx.x * TPB + tid;
    const int t   = tid & 7;
    const int tok = tokens[row];
    float x[32];
#pragma unroll
    for (int i = 0; i < 8; i++) {
        float4 a = *(const float4*)(g_tokE + tok * 32 + i * 4);
        float4 p = *(const float4*)(g_posE + t * 32 + i * 4);
        x[4 * i + 0] = a.x + p.x;
        x[4 * i + 1] = a.y + p.y;
        x[4 * i + 2] = a.z + p.z;
        x[4 * i + 3] = a.w + p.w;
    }
    stage_hilo(x, tid, S_T0, S_T1);
    __syncthreads();

    // ldmatrix address for (slot, mtile, kstep): warp stripe rows 32*wid..+31
    const int lrow = lane & 15;
    const int lcol = (lane >> 4) * 16;
#define AADDR(slot, m, kk) \
    (sb + (slot) + (wid * 32 + (m) * 16 + lrow) * 80 + (kk) * 32 + lcol)

    const int crow = wid * 32 + g;   // C-store base row for this lane
    const int ccol = 2 * tg;

#define STC(m, nt, c)                                                          \
    do {                                                                       \
        int _r = crow + (m) * 16, _n = (nt) * 8 + ccol;                        \
        *(float2*)(smc + S_C + (_r * 36 + _n) * 4) = make_float2(c[0], c[1]);  \
        *(float2*)(smc + S_C + ((_r + 8) * 36 + _n) * 4) = make_float2(c[2], c[3]); \
    } while (0)

    // ---- QKV A fragments (x hi, x lo) ----
    uint32_t aX[2][2][4], aXlo[2][2][4];
#pragma unroll
    for (int m = 0; m < 2; m++)
#pragma unroll
        for (int kk = 0; kk < 2; kk++) {
            ldmA(aX[m][kk],   AADDR(S_T0, m, kk));
            ldmA(aXlo[m][kk], AADDR(S_T1, m, kk));
        }

    // ---- round Q ----
#pragma unroll
    for (int m = 0; m < 2; m++)
#pragma unroll
        for (int nt = 0; nt < 4; nt++) {
            float c[4] = {0.f, 0.f, 0.f, 0.f};
#pragma unroll
            for (int kk = 0; kk < 2; kk++) {
                uint32_t b0, b1;
                ldfrag(b0, b1, FQ + nt * 2 + kk, lane8);
                mma16816(c, aX[m][kk], b0, b1);
            }
            STC(m, nt, c);
        }
    __syncthreads();
    float q[32];
    read_row32(q, tid);
    __syncthreads();

    // ---- round K ----
#pragma unroll
    for (int m = 0; m < 2; m++)
#pragma unroll
        for (int nt = 0; nt < 4; nt++) {
            float c[4] = {0.f, 0.f, 0.f, 0.f};
#pragma unroll
            for (int kk = 0; kk < 2; kk++) {
                uint32_t b0, b1;
                ldfrag(b0, b1, FK + nt * 2 + kk, lane8);
                mma16816(c, aX[m][kk], b0, b1);
            }
            STC(m, nt, c);
        }
    __syncthreads();

    // ---- scores + softmax (causal, fp32) ----
    const int rb = tid & ~7;
    float p[8];
#pragma unroll
    for (int s = 0; s < 8; s++) {
        const char* kr = smc + S_C + (rb + s) * 144;
        float a0 = 0, a1 = 0, a2 = 0, a3 = 0;
#pragma unroll
        for (int i = 0; i < 8; i++) {
            float4 kv = *(const float4*)(kr + i * 16);
            a0 += q[4 * i + 0] * kv.x;
            a1 += q[4 * i + 1] * kv.y;
            a2 += q[4 * i + 2] * kv.z;
            a3 += q[4 * i + 3] * kv.w;
        }
        p[s] = (a0 + a1) + (a2 + a3);
    }
    __syncthreads();   // K reads complete before V overwrites C
    float mx = -1e30f;
#pragma unroll
    for (int s = 0; s < 8; s++) if (s <= t) mx = fmaxf(mx, p[s]);
    float sum = 0.0f;
#pragma unroll
    for (int s = 0; s < 8; s++) {
        p[s] = (s <= t) ? __expf(p[s] - mx) : 0.0f;
        sum += p[s];
    }
    const float inv = 1.0f / sum;

    // ---- round V (hi/lo 3-pass) ----
#pragma unroll
    for (int m = 0; m < 2; m++)
#pragma unroll
        for (int nt = 0; nt < 4; nt++) {
            float c[4] = {0.f, 0.f, 0.f, 0.f};
#pragma unroll
            for (int kk = 0; kk < 2; kk++) {
                uint32_t b0, b1;
                ldfrag(b0, b1, FVH + nt * 2 + kk, lane8);
                mma16816(c, aX[m][kk], b0, b1);
                ldfrag(b0, b1, FVL + nt * 2 + kk, lane8);
                mma16816(c, aX[m][kk], b0, b1);
                ldfrag(b0, b1, FVH + nt * 2 + kk, lane8);
                mma16816(c, aXlo[m][kk], b0, b1);
            }
            STC(m, nt, c);
        }
    __syncthreads();

    // ---- out = attn @ V; LN1(out + x) ----
    float n1[32];
#pragma unroll
    for (int i = 0; i < 32; i++) n1[i] = 0.0f;
#pragma unroll
    for (int s = 0; s < 8; s++) {
        float w = p[s] * inv;
        const char* vr = smc + S_C + (rb + s) * 144;
#pragma unroll
        for (int i = 0; i < 8; i++) {
            float4 v4 = *(const float4*)(vr + i * 16);
            n1[4 * i + 0] += w * v4.x;
            n1[4 * i + 1] += w * v4.y;
            n1[4 * i + 2] += w * v4.z;
            n1[4 * i + 3] += w * v4.w;
        }
    }
#pragma unroll
    for (int i = 0; i < 32; i++) n1[i] += x[i];
    layernorm32(n1);
    stage_hilo(n1, tid, S_T1, S_T2);
    __syncthreads();

    // ---- W1 (two N=32 halves, A hi/lo, B hi/lo) ----
    uint32_t aH[2][2][4], aL[2][2][4];
#pragma unroll
    for (int m = 0; m < 2; m++)
#pragma unroll
        for (int kk = 0; kk < 2; kk++) {
            ldmA(aH[m][kk], AADDR(S_T1, m, kk));
            ldmA(aL[m][kk], AADDR(S_T2, m, kk));
        }
#pragma unroll 1
    for (int half = 0; half < 2; half++) {
#pragma unroll
        for (int m = 0; m < 2; m++)
#pragma unroll
            for (int nt = 0; nt < 4; nt++) {
                float c[4] = {0.f, 0.f, 0.f, 0.f};
#pragma unroll
                for (int kk = 0; kk < 2; kk++) {
                    uint32_t b0, b1;
                    int base = FW1 + half * 16 + nt * 4 + kk * 2;
                    ldfrag(b0, b1, base + 0, lane8);
                    mma16816(c, aH[m][kk], b0, b1);
                    ldfrag(b0, b1, base + 1, lane8);
                    mma16816(c, aH[m][kk], b0, b1);
                    ldfrag(b0, b1, base + 0, lane8);
                    mma16816(c, aL[m][kk], b0, b1);
                }
                STC(m, nt, c);
            }
        __syncthreads();
        float hr[32];
        read_row32(hr, tid);
#pragma unroll
        for (int i = 0; i < 32; i++) hr[i] = fmaxf(hr[i], 0.0f);
        stage_hilo(hr, tid, half ? S_T1 : S_T0, half ? S_T2 : S_T3);
        __syncthreads();
    }

    // ---- W2 (K=64 via two K=32 tile pairs) ----
#pragma unroll
    for (int m = 0; m < 2; m++) {
        uint32_t ah[4][4], al[4][4];
#pragma unroll
        for (int kg = 0; kg < 4; kg++) {
            int shi = (kg < 2) ? S_T0 : S_T1;
            int slo = (kg < 2) ? S_T3 : S_T2;
            ldmA(ah[kg], AADDR(shi, m, kg & 1));
            ldmA(al[kg], AADDR(slo, m, kg & 1));
        }
#pragma unroll
        for (int nt = 0; nt < 4; nt++) {
            float c[4] = {0.f, 0.f, 0.f, 0.f};
#pragma unroll
            for (int kg = 0; kg < 4; kg++) {
                uint32_t b0, b1;
                int base = FW2 + nt * 8 + kg * 2;
                ldfrag(b0, b1, base + 0, lane8);
                mma16816(c, ah[kg], b0, b1);
                ldfrag(b0, b1, base + 1, lane8);
                mma16816(c, ah[kg], b0, b1);
                ldfrag(b0, b1, base + 0, lane8);
                mma16816(c, al[kg], b0, b1);
            }
            STC(m, nt, c);
        }
    }
    __syncthreads();

    // ---- LN2(y + n1) ----
    float n2[32];
    read_row32(n2, tid);
#pragma unroll
    for (int i = 0; i < 32; i++) n2[i] += n1[i];
    layernorm32(n2);
    stage_hilo(n2, tid, S_T0, S_T1);
    __syncthreads();

    // ---- Wout (N padded to 32; cols 27..31 zero) ----
#pragma unroll
    for (int m = 0; m < 2; m++) {
        uint32_t ah[2][4], al[2][4];
#pragma unroll
        for (int kk = 0; kk < 2; kk++) {
            ldmA(ah[kk], AADDR(S_T0, m, kk));
            ldmA(al[kk], AADDR(S_T1, m, kk));
        }
#pragma unroll
        for (int nt = 0; nt < 4; nt++) {
            float c[4] = {0.f, 0.f, 0.f, 0.f};
#pragma unroll
            for (int kk = 0; kk < 2; kk++) {
                uint32_t b0, b1;
                int base = FWO + nt * 4 + kk * 2;
                ldfrag(b0, b1, base + 0, lane8);
                mma16816(c, ah[kk], b0, b1);
                ldfrag(b0, b1, base + 1, lane8);
                mma16816(c, ah[kk], b0, b1);
                ldfrag(b0, b1, base + 0, lane8);
                mma16816(c, al[kk], b0, b1);
            }
            STC(m, nt, c);
        }
    }
    __syncthreads();

    // ---- logits -> staged (frag area is dead) -> coalesced STG ----
    {
        float lg[28];
#pragma unroll
        for (int c = 0; c < 7; c++) {
            float4 v = *(const float4*)(smc + S_C + tid * 144 + c * 16);
            lg[4 * c] = v.x; lg[4 * c + 1] = v.y; lg[4 * c + 2] = v.z; lg[4 * c + 3] = v.w;
        }
        __syncthreads();   // all C reads done before frag area reuse is irrelevant; keeps order
        float* os = (float*)(smc + S_FRAG) + tid * 27;
#pragma unroll
        for (int j = 0; j < 27; j++) os[j] = lg[j];
    }
    __syncthreads();
    {
        const uint4* src = (const uint4*)(smc + S_FRAG);
        uint4* dst = (uint4*)(g_out + (size_t)blockIdx.x * TPB * 27);
        // 128*27 = 3456 floats = 864 uint4
#pragma unroll
        for (int b = 0; b < 864; b += TPB) {
            int i = b + tid;
            if (i < 864) dst[i] = src[i];
        }
    }
#undef AADDR
#undef STC
}

extern "C" void kernel_launch(void* const* d_in, const int* in_sizes, int n_in,
                              void* d_out, int out_size) {
    const int*   tokens = (const int*)d_in[0];
    const float* tokE   = (const float*)d_in[1];
    const float* posE   = (const float*)d_in[2];
    const float* Wq     = (const float*)d_in[3];
    const float* Wk     = (const float*)d_in[4];
    const float* Wv     = (const float*)d_in[5];
    const float* W1     = (const float*)d_in[6];
    const float* W2     = (const float*)d_in[7];
    const float* Wout   = (const float*)d_in[8];
    float*       out    = (float*)d_out;

    cudaFuncSetAttribute(mt_mma_kernel,
                         cudaFuncAttributeMaxDynamicSharedMemorySize, SMEM_TOTAL);

    const int rows   = in_sizes[0];   // B*T = 1048576
    const int blocks = rows / TPB;    // 8192
    mt_mma_kernel<<<blocks, TPB, SMEM_TOTAL>>>(tokens, tokE, posE, Wq, Wk, Wv,
                                               W1, W2, Wout, out);
}

// round 6
// speedup vs baseline: 1.2050x; 1.2050x over previous
#include <cuda_runtime.h>
#include <cuda_bf16.h>
#include <cstdint>

#define TPB 128
#define RPB 256   // rows per block (2 per thread)

// ---------------- weights in constant memory (off the L1 crossbar) ----------
__constant__ float c_W1[2048];   // [32 x 64] row-major, same as g_W1
__constant__ float c_W2[2048];   // [64 x 32] row-major, same as g_W2

// ---------------- packed f32x2 helpers (Blackwell FFMA2 path) ----------------
__device__ __forceinline__ unsigned long long fma2(unsigned long long a,
                                                   unsigned long long b,
                                                   unsigned long long c) {
    unsigned long long d;
    asm("fma.rn.f32x2 %0, %1, %2, %3;" : "=l"(d) : "l"(a), "l"(b), "l"(c));
    return d;
}
__device__ __forceinline__ unsigned long long add2(unsigned long long a,
                                                   unsigned long long b) {
    unsigned long long d;
    asm("add.rn.f32x2 %0, %1, %2;" : "=l"(d) : "l"(a), "l"(b));
    return d;
}
__device__ __forceinline__ unsigned long long pack2(float lo, float hi) {
    unsigned long long r;
    asm("mov.b64 %0, {%1, %2};" : "=l"(r) : "f"(lo), "f"(hi));
    return r;
}
__device__ __forceinline__ void unpack2(float& lo, float& hi, unsigned long long v) {
    asm("mov.b64 {%0, %1}, %2;" : "=f"(lo), "=f"(hi) : "l"(v));
}

// ---------------- smem layout (floats) ----------------
static constexpr int OFF_WQ   = 0;
static constexpr int OFF_WK   = 1024;
static constexpr int OFF_WV   = 2048;
static constexpr int OFF_WOUT = 3072;   // 32 x 28 padded
static constexpr int OFF_TOKE = 3968;   // 27 x 36
static constexpr int OFF_POSE = 4940;   // 8 x 36
static constexpr int OFF_KV   = 5228;   // 256 x 36 -- K, then V, then out stage
static constexpr int SMEM_FLOATS = 14444;
static constexpr int SMEM_BYTES  = SMEM_FLOATS * 4;   // 57776 B -> 3 CTAs/SM

// dual-row rank-32 matvec: one weight LDS.128 feeds 4 FFMA2
#define MATVEC32_DUAL(a0, a1, v0, v1, Wsm)                                    \
    do {                                                                      \
        _Pragma("unroll") for (int _i = 0; _i < 16; _i++) {                   \
            a0[_i] = 0ULL; a1[_i] = 0ULL;                                     \
        }                                                                     \
        _Pragma("unroll") for (int _e = 0; _e < 32; _e++) {                   \
            unsigned long long _b0 = pack2((v0)[_e], (v0)[_e]);               \
            unsigned long long _b1 = pack2((v1)[_e], (v1)[_e]);               \
            const ulonglong2* _w = (const ulonglong2*)((Wsm) + _e * 32);      \
            _Pragma("unroll") for (int _i = 0; _i < 8; _i++) {                \
                ulonglong2 _ww = _w[_i];                                      \
                a0[2 * _i]     = fma2(_b0, _ww.x, a0[2 * _i]);                \
                a0[2 * _i + 1] = fma2(_b0, _ww.y, a0[2 * _i + 1]);            \
                a1[2 * _i]     = fma2(_b1, _ww.x, a1[2 * _i]);                \
                a1[2 * _i + 1] = fma2(_b1, _ww.y, a1[2 * _i + 1]);            \
            }                                                                 \
        }                                                                     \
    } while (0)

extern __shared__ float sm[];

__device__ __forceinline__ void layernorm32(float* v) {
    float s1 = 0.0f, s2 = 0.0f;
#pragma unroll
    for (int e = 0; e < 32; e++) { s1 += v[e]; s2 += v[e] * v[e]; }
    float mu  = s1 * (1.0f / 32.0f);
    float var = s2 * (1.0f / 32.0f) - mu * mu;
    float rs  = rsqrtf(var + 1e-5f);
#pragma unroll
    for (int e = 0; e < 32; e++) v[e] = (v[e] - mu) * rs;
}

__global__ void __launch_bounds__(TPB, 3)
mt_kernel(const int* __restrict__ tokens,
          const float* __restrict__ g_tokE, const float* __restrict__ g_posE,
          const float* __restrict__ g_Wq,  const float* __restrict__ g_Wk,
          const float* __restrict__ g_Wv,  const float* __restrict__ g_Wout,
          float* __restrict__ g_out)
{
    float* s_Wq   = sm + OFF_WQ;
    float* s_Wk   = sm + OFF_WK;
    float* s_Wv   = sm + OFF_WV;
    float* s_Wout = sm + OFF_WOUT;
    float* s_tokE = sm + OFF_TOKE;
    float* s_posE = sm + OFF_POSE;
    float* s_KV   = sm + OFF_KV;

    const int tid = threadIdx.x;

    // ---- cooperative staging (QKV, Wout, embeddings) ----
#pragma unroll
    for (int b = 0; b < 1024; b += TPB * 4) {
        int i = b + tid * 4;
        if (i < 1024) {
            *(float4*)(s_Wq + i) = *(const float4*)(g_Wq + i);
            *(float4*)(s_Wk + i) = *(const float4*)(g_Wk + i);
            *(float4*)(s_Wv + i) = *(const float4*)(g_Wv + i);
        }
    }
    for (int i = tid; i < 32 * 28; i += TPB) {
        int e = i / 28, c = i % 28;
        s_Wout[i] = (c < 27) ? g_Wout[e * 27 + c] : 0.0f;
    }
    for (int i = tid; i < 27 * 32; i += TPB) {
        int r = i >> 5, c = i & 31;
        s_tokE[r * 36 + c] = g_tokE[i];
    }
    for (int i = tid; i < 8 * 32; i += TPB) {
        int r = i >> 5, c = i & 31;
        s_posE[r * 36 + c] = g_posE[i];
    }
    __syncthreads();

    const int r0  = blockIdx.x * RPB + tid;  // first row for this thread
    const int r1  = r0 + TPB;                // second row
    const int t   = tid & 7;                 // same t for both rows
    const int tok0 = tokens[r0];
    const int tok1 = tokens[r1];

    // ---- x = tok_emb[tok] + pos_emb[t] ----
    float x0[32], x1[32];
#pragma unroll
    for (int i = 0; i < 8; i++) {
        float4 p  = *(const float4*)(s_posE + t * 36 + i * 4);
        float4 a0 = *(const float4*)(s_tokE + tok0 * 36 + i * 4);
        float4 a1 = *(const float4*)(s_tokE + tok1 * 36 + i * 4);
        x0[4 * i + 0] = a0.x + p.x;  x1[4 * i + 0] = a1.x + p.x;
        x0[4 * i + 1] = a0.y + p.y;  x1[4 * i + 1] = a1.y + p.y;
        x0[4 * i + 2] = a0.z + p.z;  x1[4 * i + 2] = a1.z + p.z;
        x0[4 * i + 3] = a0.w + p.w;  x1[4 * i + 3] = a1.w + p.w;
    }

    // ---- K into shared buffer (time-multiplexed K -> V) ----
    {
        unsigned long long k0[16], k1[16];
        MATVEC32_DUAL(k0, k1, x0, x1, s_Wk);
        ulonglong2* kr0 = (ulonglong2*)(s_KV + tid * 36);
        ulonglong2* kr1 = (ulonglong2*)(s_KV + (TPB + tid) * 36);
#pragma unroll
        for (int i = 0; i < 8; i++) {
            kr0[i] = make_ulonglong2(k0[2 * i], k0[2 * i + 1]);
            kr1[i] = make_ulonglong2(k1[2 * i], k1[2 * i + 1]);
        }
    }
    // Q in regs
    unsigned long long q0[16], q1[16];
    MATVEC32_DUAL(q0, q1, x0, x1, s_Wq);
    __syncwarp();   // K of this warp's batches visible

    // ---- scores (both rows) ----
    const int rb0 = (tid & ~7) * 36;
    const int rb1 = (TPB + (tid & ~7)) * 36;
    float p0[8], p1[8];   // scores, then probabilities in-place
#pragma unroll
    for (int s = 0; s < 8; s++) {
        const ulonglong2* ka = (const ulonglong2*)(s_KV + rb0 + s * 36);
        const ulonglong2* kb = (const ulonglong2*)(s_KV + rb1 + s * 36);
        unsigned long long a0 = 0, a1 = 0, b0 = 0, b1 = 0;
#pragma unroll
        for (int i = 0; i < 8; i++) {
            ulonglong2 kva = ka[i];
            ulonglong2 kvb = kb[i];
            a0 = fma2(q0[2 * i], kva.x, a0);
            a1 = fma2(q0[2 * i + 1], kva.y, a1);
            b0 = fma2(q1[2 * i], kvb.x, b0);
            b1 = fma2(q1[2 * i + 1], kvb.y, b1);
        }
        a0 = add2(a0, a1);
        b0 = add2(b0, b1);
        float lo, hi;
        unpack2(lo, hi, a0); p0[s] = lo + hi;
        unpack2(lo, hi, b0); p1[s] = lo + hi;
    }
    __syncwarp();   // all lanes done reading K before V overwrites buffer

    // ---- softmax (causal: s <= t) ----
    float m0 = -1e30f, m1 = -1e30f;
#pragma unroll
    for (int s = 0; s < 8; s++) {
        if (s <= t) { m0 = fmaxf(m0, p0[s]); m1 = fmaxf(m1, p1[s]); }
    }
    float sum0 = 0.0f, sum1 = 0.0f;
#pragma unroll
    for (int s = 0; s < 8; s++) {
        p0[s] = (s <= t) ? __expf(p0[s] - m0) : 0.0f;
        p1[s] = (s <= t) ? __expf(p1[s] - m1) : 0.0f;
        sum0 += p0[s]; sum1 += p1[s];
    }
    const float inv0 = 1.0f / sum0;
    const float inv1 = 1.0f / sum1;

    // ---- V into the SAME shared buffer ----
    {
        unsigned long long v0[16], v1[16];
        MATVEC32_DUAL(v0, v1, x0, x1, s_Wv);
        ulonglong2* vr0 = (ulonglong2*)(s_KV + tid * 36);
        ulonglong2* vr1 = (ulonglong2*)(s_KV + (TPB + tid) * 36);
#pragma unroll
        for (int i = 0; i < 8; i++) {
            vr0[i] = make_ulonglong2(v0[2 * i], v0[2 * i + 1]);
            vr1[i] = make_ulonglong2(v1[2 * i], v1[2 * i + 1]);
        }
    }
    __syncwarp();   // V visible

    // ---- out = attn @ V ----
    unsigned long long o0[16], o1[16];
#pragma unroll
    for (int i = 0; i < 16; i++) { o0[i] = 0ULL; o1[i] = 0ULL; }
#pragma unroll
    for (int s = 0; s < 8; s++) {
        float a = p0[s] * inv0;
        float b = p1[s] * inv1;
        unsigned long long aa = pack2(a, a);
        unsigned long long bb = pack2(b, b);
        const ulonglong2* va = (const ulonglong2*)(s_KV + rb0 + s * 36);
        const ulonglong2* vb = (const ulonglong2*)(s_KV + rb1 + s * 36);
#pragma unroll
        for (int i = 0; i < 8; i++) {
            ulonglong2 wa = va[i], wb = vb[i];
            o0[2 * i]     = fma2(aa, wa.x, o0[2 * i]);
            o0[2 * i + 1] = fma2(aa, wa.y, o0[2 * i + 1]);
            o1[2 * i]     = fma2(bb, wb.x, o1[2 * i]);
            o1[2 * i + 1] = fma2(bb, wb.y, o1[2 * i + 1]);
        }
    }

    // ---- LN1(out + x) ----
    float n1a[32], n1b[32];
#pragma unroll
    for (int i = 0; i < 16; i++) {
        float lo, hi;
        unpack2(lo, hi, o0[i]);
        n1a[2 * i] = lo + x0[2 * i];  n1a[2 * i + 1] = hi + x0[2 * i + 1];
        unpack2(lo, hi, o1[i]);
        n1b[2 * i] = lo + x1[2 * i];  n1b[2 * i + 1] = hi + x1[2 * i + 1];
    }
    layernorm32(n1a);
    layernorm32(n1b);

    // ---- MLP: relu(n1 @ W1) @ W2, weights from CONSTANT memory ----
    unsigned long long y0[16], y1[16];
#pragma unroll
    for (int i = 0; i < 16; i++) { y0[i] = 0ULL; y1[i] = 0ULL; }
#pragma unroll 1
    for (int c = 0; c < 8; c++) {
        unsigned long long h0[4], h1[4];
#pragma unroll
        for (int i = 0; i < 4; i++) { h0[i] = 0ULL; h1[i] = 0ULL; }
#pragma unroll
        for (int e = 0; e < 32; e++) {
            unsigned long long b0 = pack2(n1a[e], n1a[e]);
            unsigned long long b1 = pack2(n1b[e], n1b[e]);
            const ulonglong2* w = (const ulonglong2*)(c_W1 + e * 64 + c * 8);
#pragma unroll
            for (int i = 0; i < 2; i++) {
                ulonglong2 ww = w[i];
                h0[2 * i]     = fma2(b0, ww.x, h0[2 * i]);
                h0[2 * i + 1] = fma2(b0, ww.y, h0[2 * i + 1]);
                h1[2 * i]     = fma2(b1, ww.x, h1[2 * i]);
                h1[2 * i + 1] = fma2(b1, ww.y, h1[2 * i + 1]);
            }
        }
#pragma unroll
        for (int j = 0; j < 4; j++) {
            float ha0, ha1, hb0, hb1;
            unpack2(ha0, ha1, h0[j]);
            unpack2(hb0, hb1, h1[j]);
            ha0 = fmaxf(ha0, 0.0f); ha1 = fmaxf(ha1, 0.0f);
            hb0 = fmaxf(hb0, 0.0f); hb1 = fmaxf(hb1, 0.0f);
            const ulonglong2* wa =
                (const ulonglong2*)(c_W2 + (c * 8 + 2 * j) * 32);
            {
                unsigned long long pa = pack2(ha0, ha0);
                unsigned long long pb = pack2(hb0, hb0);
#pragma unroll
                for (int i = 0; i < 8; i++) {
                    ulonglong2 ww = wa[i];
                    y0[2 * i]     = fma2(pa, ww.x, y0[2 * i]);
                    y0[2 * i + 1] = fma2(pa, ww.y, y0[2 * i + 1]);
                    y1[2 * i]     = fma2(pb, ww.x, y1[2 * i]);
                    y1[2 * i + 1] = fma2(pb, ww.y, y1[2 * i + 1]);
                }
            }
            {
                unsigned long long pa = pack2(ha1, ha1);
                unsigned long long pb = pack2(hb1, hb1);
                const ulonglong2* wb = wa + 8;  // next W2 row
#pragma unroll
                for (int i = 0; i < 8; i++) {
                    ulonglong2 ww = wb[i];
                    y0[2 * i]     = fma2(pa, ww.x, y0[2 * i]);
                    y0[2 * i + 1] = fma2(pa, ww.y, y0[2 * i + 1]);
                    y1[2 * i]     = fma2(pb, ww.x, y1[2 * i]);
                    y1[2 * i + 1] = fma2(pb, ww.y, y1[2 * i + 1]);
                }
            }
        }
    }

    // ---- LN2(y + n1) ----
    float n2a[32], n2b[32];
#pragma unroll
    for (int i = 0; i < 16; i++) {
        float lo, hi;
        unpack2(lo, hi, y0[i]);
        n2a[2 * i] = lo + n1a[2 * i];  n2a[2 * i + 1] = hi + n1a[2 * i + 1];
        unpack2(lo, hi, y1[i]);
        n2b[2 * i] = lo + n1b[2 * i];  n2b[2 * i + 1] = hi + n1b[2 * i + 1];
    }
    layernorm32(n2a);
    layernorm32(n2b);

    // ---- logits = n2 @ Wout (28-padded; col 27 is zero) ----
    unsigned long long l0[14], l1[14];
#pragma unroll
    for (int i = 0; i < 14; i++) { l0[i] = 0ULL; l1[i] = 0ULL; }
#pragma unroll
    for (int e = 0; e < 32; e++) {
        unsigned long long b0 = pack2(n2a[e], n2a[e]);
        unsigned long long b1 = pack2(n2b[e], n2b[e]);
        const ulonglong2* w = (const ulonglong2*)(sm + OFF_WOUT + e * 28);
#pragma unroll
        for (int i = 0; i < 7; i++) {
            ulonglong2 ww = w[i];
            l0[2 * i]     = fma2(b0, ww.x, l0[2 * i]);
            l0[2 * i + 1] = fma2(b0, ww.y, l0[2 * i + 1]);
            l1[2 * i]     = fma2(b1, ww.x, l1[2 * i]);
            l1[2 * i + 1] = fma2(b1, ww.y, l1[2 * i + 1]);
        }
    }

    // ---- stage outputs in smem (reuse KV buffer), then coalesced STG ----
    __syncthreads();   // all warps done with their KV region
    float* s_out = s_KV;  // 256*27 = 6912 floats <= 9216
    {
        float* oa = s_out + tid * 27;
        float* ob = s_out + (TPB + tid) * 27;
#pragma unroll
        for (int i = 0; i < 13; i++) {
            float lo, hi;
            unpack2(lo, hi, l0[i]); oa[2 * i] = lo; oa[2 * i + 1] = hi;
            unpack2(lo, hi, l1[i]); ob[2 * i] = lo; ob[2 * i + 1] = hi;
        }
        float lo, hi;
        unpack2(lo, hi, l0[13]); oa[26] = lo;
        unpack2(lo, hi, l1[13]); ob[26] = lo;
    }
    __syncthreads();
    {
        const float4* src = (const float4*)s_out;
        float4* dst = (float4*)(g_out + (size_t)blockIdx.x * RPB * 27);
        // 256*27 = 6912 floats = 1728 float4
#pragma unroll
        for (int b = 0; b < 1728; b += TPB) {
            int i = b + tid;
            if (i < 1728) dst[i] = src[i];
        }
    }
}

extern "C" void kernel_launch(void* const* d_in, const int* in_sizes, int n_in,
                              void* d_out, int out_size) {
    const int*   tokens = (const int*)d_in[0];
    const float* tokE   = (const float*)d_in[1];
    const float* posE   = (const float*)d_in[2];
    const float* Wq     = (const float*)d_in[3];
    const float* Wk     = (const float*)d_in[4];
    const float* Wv     = (const float*)d_in[5];
    const float* W1     = (const float*)d_in[6];
    const float* W2     = (const float*)d_in[7];
    const float* Wout   = (const float*)d_in[8];
    float*       out    = (float*)d_out;

    // weights -> constant bank (D2D memcpy nodes; graph-capturable)
    cudaMemcpyToSymbolAsync(c_W1, W1, 2048 * sizeof(float), 0,
                            cudaMemcpyDeviceToDevice, 0);
    cudaMemcpyToSymbolAsync(c_W2, W2, 2048 * sizeof(float), 0,
                            cudaMemcpyDeviceToDevice, 0);

    cudaFuncSetAttribute(mt_kernel, cudaFuncAttributeMaxDynamicSharedMemorySize,
                         SMEM_BYTES);

    const int rows   = in_sizes[0];   // B*T = 1048576
    const int blocks = rows / RPB;    // 4096
    mt_kernel<<<blocks, TPB, SMEM_BYTES>>>(tokens, tokE, posE, Wq, Wk, Wv,
                                           Wout, out);
}

// round 7
// speedup vs baseline: 1.7059x; 1.4157x over previous
#include <cuda_runtime.h>
#include <cstdint>

#define TPB 128
#define RPB 256   // rows per block (2 per thread)

// ---------------- precomputed tables (device globals; no allocation) --------
__device__ float g_Qtab[216 * 32];
__device__ float g_Ktab[216 * 32];
__device__ float g_Vtab[216 * 32];
__device__ float g_Stab[216 * 216];   // [(tok_t*8+t)*216 + tok_s*8 + s]

// ---------------- packed f32x2 helpers ----------------
__device__ __forceinline__ unsigned long long fma2(unsigned long long a,
                                                   unsigned long long b,
                                                   unsigned long long c) {
    unsigned long long d;
    asm("fma.rn.f32x2 %0, %1, %2, %3;" : "=l"(d) : "l"(a), "l"(b), "l"(c));
    return d;
}
__device__ __forceinline__ unsigned long long pack2(float lo, float hi) {
    unsigned long long r;
    asm("mov.b64 %0, {%1, %2};" : "=l"(r) : "f"(lo), "f"(hi));
    return r;
}
__device__ __forceinline__ void unpack2(float& lo, float& hi, unsigned long long v) {
    asm("mov.b64 {%0, %1}, %2;" : "=f"(lo), "=f"(hi) : "l"(v));
}

// ---------------- pre-kernel 1: QKV tables (216 rows) ----------------
__global__ void qkv_tab_kernel(const float* __restrict__ tokE,
                               const float* __restrict__ posE,
                               const float* __restrict__ Wq,
                               const float* __restrict__ Wk,
                               const float* __restrict__ Wv) {
    int r = blockIdx.x * blockDim.x + threadIdx.x;
    if (r >= 216) return;
    int tok = r >> 3, t = r & 7;
    float x[32];
#pragma unroll
    for (int d = 0; d < 32; d++) x[d] = tokE[tok * 32 + d] + posE[t * 32 + d];
#pragma unroll 4
    for (int n = 0; n < 32; n++) {
        float q = 0.f, k = 0.f, v = 0.f;
#pragma unroll
        for (int d = 0; d < 32; d++) {
            q += x[d] * Wq[d * 32 + n];
            k += x[d] * Wk[d * 32 + n];
            v += x[d] * Wv[d * 32 + n];
        }
        g_Qtab[r * 32 + n] = q;
        g_Ktab[r * 32 + n] = k;
        g_Vtab[r * 32 + n] = v;
    }
}

// ---------------- pre-kernel 2: score table (216 x 216) ----------------
__global__ void stab_kernel() {
    int e = blockIdx.x * blockDim.x + threadIdx.x;
    if (e >= 216 * 216) return;
    int rq = e / 216, rk = e - rq * 216;
    const float* Q = g_Qtab + rq * 32;
    const float* K = g_Ktab + rk * 32;
    float s = 0.f;
#pragma unroll
    for (int d = 0; d < 32; d++) s += Q[d] * K[d];
    g_Stab[e] = s;
}

// ---------------- main kernel smem layout (floats) ----------------
static constexpr int OFF_W1   = 0;      // 32 x 64
static constexpr int OFF_W2   = 2048;   // 64 x 32
static constexpr int OFF_WOUT = 4096;   // 32 x 28 padded
static constexpr int OFF_TOKE = 4992;   // 27 x 36
static constexpr int OFF_POSE = 5964;   // 8 x 36
static constexpr int OFF_VT   = 6252;   // 216 x 36  (V table; reused for out)
static constexpr int SMEM_FLOATS = 14028;
static constexpr int SMEM_BYTES  = SMEM_FLOATS * 4;   // 56112 B

extern __shared__ float sm[];

__device__ __forceinline__ void layernorm32(float* v) {
    float s1 = 0.0f, s2 = 0.0f;
#pragma unroll
    for (int e = 0; e < 32; e++) { s1 += v[e]; s2 += v[e] * v[e]; }
    float mu  = s1 * (1.0f / 32.0f);
    float var = s2 * (1.0f / 32.0f) - mu * mu;
    float rs  = rsqrtf(var + 1e-5f);
#pragma unroll
    for (int e = 0; e < 32; e++) v[e] = (v[e] - mu) * rs;
}

__global__ void __launch_bounds__(TPB, 3)
mt_kernel(const int* __restrict__ tokens,
          const float* __restrict__ g_tokE, const float* __restrict__ g_posE,
          const float* __restrict__ g_W1,  const float* __restrict__ g_W2,
          const float* __restrict__ g_Wout,
          float* __restrict__ g_out)
{
    float* s_W1   = sm + OFF_W1;
    float* s_W2   = sm + OFF_W2;
    float* s_Wout = sm + OFF_WOUT;
    float* s_tokE = sm + OFF_TOKE;
    float* s_posE = sm + OFF_POSE;
    float* s_VT   = sm + OFF_VT;

    const int tid = threadIdx.x;

    // ---- cooperative staging ----
#pragma unroll
    for (int b = 0; b < 2048; b += TPB * 4) {
        int i = b + tid * 4;
        *(float4*)(s_W1 + i) = *(const float4*)(g_W1 + i);
        *(float4*)(s_W2 + i) = *(const float4*)(g_W2 + i);
    }
    for (int i = tid; i < 32 * 28; i += TPB) {
        int e = i / 28, c = i % 28;
        s_Wout[i] = (c < 27) ? g_Wout[e * 27 + c] : 0.0f;
    }
    for (int i = tid; i < 27 * 32; i += TPB) {
        int r = i >> 5, c = i & 31;
        s_tokE[r * 36 + c] = g_tokE[i];
    }
    for (int i = tid; i < 8 * 32; i += TPB) {
        int r = i >> 5, c = i & 31;
        s_posE[r * 36 + c] = g_posE[i];
    }
    for (int i = tid; i < 216 * 8; i += TPB) {   // V table, stride-36 padded
        int r = i >> 3, c = i & 7;
        *(float4*)(s_VT + r * 36 + c * 4) = *(const float4*)(g_Vtab + r * 32 + c * 4);
    }
    __syncthreads();

    const int r0 = blockIdx.x * RPB + tid;   // first row
    const int r1 = r0 + TPB;                 // second row
    const int t  = tid & 7;
    const int b0 = r0 >> 3;                  // batch of row0
    const int b1 = b0 + 16;                  // batch of row1

    // batch token sequences (s = 0..7)
    const int4 ta0 = *(const int4*)(tokens + b0 * 8);
    const int4 tb0 = *(const int4*)(tokens + b0 * 8 + 4);
    const int4 ta1 = *(const int4*)(tokens + b1 * 8);
    const int4 tb1 = *(const int4*)(tokens + b1 * 8 + 4);
    const int tk0[8] = {ta0.x, ta0.y, ta0.z, ta0.w, tb0.x, tb0.y, tb0.z, tb0.w};
    const int tk1[8] = {ta1.x, ta1.y, ta1.z, ta1.w, tb1.x, tb1.y, tb1.z, tb1.w};
    const int tok0 = tk0[t] & 31;   // own tokens (t known per-thread but tk is
    const int tok1 = tk1[t] & 31;   //  unrolled-literal; &31 keeps ptxas happy)

    // ---- scores from table (8 scattered L2 loads per row) ----
    const int sb0 = (tok0 * 8 + t) * 216;
    const int sb1 = (tok1 * 8 + t) * 216;
    float p0[8], p1[8];
#pragma unroll
    for (int s = 0; s < 8; s++) {
        p0[s] = __ldg(g_Stab + sb0 + tk0[s] * 8 + s);
        p1[s] = __ldg(g_Stab + sb1 + tk1[s] * 8 + s);
    }

    // ---- softmax (causal: s <= t) ----
    float m0 = -1e30f, m1 = -1e30f;
#pragma unroll
    for (int s = 0; s < 8; s++) {
        if (s <= t) { m0 = fmaxf(m0, p0[s]); m1 = fmaxf(m1, p1[s]); }
    }
    float sum0 = 0.0f, sum1 = 0.0f;
#pragma unroll
    for (int s = 0; s < 8; s++) {
        p0[s] = (s <= t) ? __expf(p0[s] - m0) : 0.0f;
        p1[s] = (s <= t) ? __expf(p1[s] - m1) : 0.0f;
        sum0 += p0[s]; sum1 += p1[s];
    }
    const float inv0 = 1.0f / sum0;
    const float inv1 = 1.0f / sum1;

    // ---- out = attn @ V (V rows from smem table) ----
    unsigned long long o0[16], o1[16];
#pragma unroll
    for (int i = 0; i < 16; i++) { o0[i] = 0ULL; o1[i] = 0ULL; }
#pragma unroll
    for (int s = 0; s < 8; s++) {
        float a = p0[s] * inv0;
        float b = p1[s] * inv1;
        unsigned long long aa = pack2(a, a);
        unsigned long long bb = pack2(b, b);
        const ulonglong2* va = (const ulonglong2*)(s_VT + (tk0[s] * 8 + s) * 36);
        const ulonglong2* vb = (const ulonglong2*)(s_VT + (tk1[s] * 8 + s) * 36);
#pragma unroll
        for (int i = 0; i < 8; i++) {
            ulonglong2 wa = va[i], wb = vb[i];
            o0[2 * i]     = fma2(aa, wa.x, o0[2 * i]);
            o0[2 * i + 1] = fma2(aa, wa.y, o0[2 * i + 1]);
            o1[2 * i]     = fma2(bb, wb.x, o1[2 * i]);
            o1[2 * i + 1] = fma2(bb, wb.y, o1[2 * i + 1]);
        }
    }

    // ---- LN1(out + x), x rebuilt from tokE/posE smem ----
    float n1a[32], n1b[32];
#pragma unroll
    for (int i = 0; i < 8; i++) {
        float4 pp = *(const float4*)(s_posE + t * 36 + i * 4);
        float4 xa = *(const float4*)(s_tokE + tok0 * 36 + i * 4);
        float4 xb = *(const float4*)(s_tokE + tok1 * 36 + i * 4);
        float lo, hi;
        unpack2(lo, hi, o0[2 * i]);
        n1a[4 * i + 0] = lo + xa.x + pp.x;
        n1a[4 * i + 1] = hi + xa.y + pp.y;
        unpack2(lo, hi, o0[2 * i + 1]);
        n1a[4 * i + 2] = lo + xa.z + pp.z;
        n1a[4 * i + 3] = hi + xa.w + pp.w;
        unpack2(lo, hi, o1[2 * i]);
        n1b[4 * i + 0] = lo + xb.x + pp.x;
        n1b[4 * i + 1] = hi + xb.y + pp.y;
        unpack2(lo, hi, o1[2 * i + 1]);
        n1b[4 * i + 2] = lo + xb.z + pp.z;
        n1b[4 * i + 3] = hi + xb.w + pp.w;
    }
    layernorm32(n1a);
    layernorm32(n1b);

    // ---- MLP: relu(n1 @ W1) @ W2, h in 8 chunks of 8 ----
    unsigned long long y0[16], y1[16];
#pragma unroll
    for (int i = 0; i < 16; i++) { y0[i] = 0ULL; y1[i] = 0ULL; }
#pragma unroll 1
    for (int c = 0; c < 8; c++) {
        unsigned long long h0[4], h1[4];
#pragma unroll
        for (int i = 0; i < 4; i++) { h0[i] = 0ULL; h1[i] = 0ULL; }
#pragma unroll
        for (int e = 0; e < 32; e++) {
            unsigned long long b0v = pack2(n1a[e], n1a[e]);
            unsigned long long b1v = pack2(n1b[e], n1b[e]);
            const ulonglong2* w = (const ulonglong2*)(s_W1 + e * 64 + c * 8);
#pragma unroll
            for (int i = 0; i < 2; i++) {
                ulonglong2 ww = w[i];
                h0[2 * i]     = fma2(b0v, ww.x, h0[2 * i]);
                h0[2 * i + 1] = fma2(b0v, ww.y, h0[2 * i + 1]);
                h1[2 * i]     = fma2(b1v, ww.x, h1[2 * i]);
                h1[2 * i + 1] = fma2(b1v, ww.y, h1[2 * i + 1]);
            }
        }
#pragma unroll
        for (int j = 0; j < 4; j++) {
            float ha0, ha1, hb0, hb1;
            unpack2(ha0, ha1, h0[j]);
            unpack2(hb0, hb1, h1[j]);
            ha0 = fmaxf(ha0, 0.0f); ha1 = fmaxf(ha1, 0.0f);
            hb0 = fmaxf(hb0, 0.0f); hb1 = fmaxf(hb1, 0.0f);
            const ulonglong2* wa =
                (const ulonglong2*)(s_W2 + (c * 8 + 2 * j) * 32);
            {
                unsigned long long pa = pack2(ha0, ha0);
                unsigned long long pb = pack2(hb0, hb0);
#pragma unroll
                for (int i = 0; i < 8; i++) {
                    ulonglong2 ww = wa[i];
                    y0[2 * i]     = fma2(pa, ww.x, y0[2 * i]);
                    y0[2 * i + 1] = fma2(pa, ww.y, y0[2 * i + 1]);
                    y1[2 * i]     = fma2(pb, ww.x, y1[2 * i]);
                    y1[2 * i + 1] = fma2(pb, ww.y, y1[2 * i + 1]);
                }
            }
            {
                unsigned long long pa = pack2(ha1, ha1);
                unsigned long long pb = pack2(hb1, hb1);
                const ulonglong2* wb = wa + 8;
#pragma unroll
                for (int i = 0; i < 8; i++) {
                    ulonglong2 ww = wb[i];
                    y0[2 * i]     = fma2(pa, ww.x, y0[2 * i]);
                    y0[2 * i + 1] = fma2(pa, ww.y, y0[2 * i + 1]);
                    y1[2 * i]     = fma2(pb, ww.x, y1[2 * i]);
                    y1[2 * i + 1] = fma2(pb, ww.y, y1[2 * i + 1]);
                }
            }
        }
    }

    // ---- LN2(y + n1) ----
    float n2a[32], n2b[32];
#pragma unroll
    for (int i = 0; i < 16; i++) {
        float lo, hi;
        unpack2(lo, hi, y0[i]);
        n2a[2 * i] = lo + n1a[2 * i];  n2a[2 * i + 1] = hi + n1a[2 * i + 1];
        unpack2(lo, hi, y1[i]);
        n2b[2 * i] = lo + n1b[2 * i];  n2b[2 * i + 1] = hi + n1b[2 * i + 1];
    }
    layernorm32(n2a);
    layernorm32(n2b);

    // ---- logits = n2 @ Wout (28-padded; col 27 is zero) ----
    unsigned long long l0[14], l1[14];
#pragma unroll
    for (int i = 0; i < 14; i++) { l0[i] = 0ULL; l1[i] = 0ULL; }
#pragma unroll
    for (int e = 0; e < 32; e++) {
        unsigned long long b0v = pack2(n2a[e], n2a[e]);
        unsigned long long b1v = pack2(n2b[e], n2b[e]);
        const ulonglong2* w = (const ulonglong2*)(s_Wout + e * 28);
#pragma unroll
        for (int i = 0; i < 7; i++) {
            ulonglong2 ww = w[i];
            l0[2 * i]     = fma2(b0v, ww.x, l0[2 * i]);
            l0[2 * i + 1] = fma2(b0v, ww.y, l0[2 * i + 1]);
            l1[2 * i]     = fma2(b1v, ww.x, l1[2 * i]);
            l1[2 * i + 1] = fma2(b1v, ww.y, l1[2 * i + 1]);
        }
    }

    // ---- stage outputs in smem (reuse V-table region), coalesced STG ----
    __syncthreads();   // all threads done reading the V table
    float* s_out = s_VT;   // 256*27 = 6912 floats <= 7776
    {
        float* oa = s_out + tid * 27;
        float* ob = s_out + (TPB + tid) * 27;
#pragma unroll
        for (int i = 0; i < 13; i++) {
            float lo, hi;
            unpack2(lo, hi, l0[i]); oa[2 * i] = lo; oa[2 * i + 1] = hi;
            unpack2(lo, hi, l1[i]); ob[2 * i] = lo; ob[2 * i + 1] = hi;
        }
        float lo, hi;
        unpack2(lo, hi, l0[13]); oa[26] = lo;
        unpack2(lo, hi, l1[13]); ob[26] = lo;
    }
    __syncthreads();
    {
        const float4* src = (const float4*)s_out;
        float4* dst = (float4*)(g_out + (size_t)blockIdx.x * RPB * 27);
#pragma unroll
        for (int b = 0; b < 1728; b += TPB) {
            int i = b + tid;
            if (i < 1728) dst[i] = src[i];
        }
    }
}

extern "C" void kernel_launch(void* const* d_in, const int* in_sizes, int n_in,
                              void* d_out, int out_size) {
    const int*   tokens = (const int*)d_in[0];
    const float* tokE   = (const float*)d_in[1];
    const float* posE   = (const float*)d_in[2];
    const float* Wq     = (const float*)d_in[3];
    const float* Wk     = (const float*)d_in[4];
    const float* Wv     = (const float*)d_in[5];
    const float* W1     = (const float*)d_in[6];
    const float* W2     = (const float*)d_in[7];
    const float* Wout   = (const float*)d_in[8];
    float*       out    = (float*)d_out;

    cudaFuncSetAttribute(mt_kernel, cudaFuncAttributeMaxDynamicSharedMemorySize,
                         SMEM_BYTES);

    // table precompute (tiny), then the fused main kernel — same stream
    qkv_tab_kernel<<<1, 256>>>(tokE, posE, Wq, Wk, Wv);
    stab_kernel<<<(216 * 216 + 255) / 256, 256>>>();

    const int rows   = in_sizes[0];   // B*T = 1048576
    const int blocks = rows / RPB;    // 4096
    mt_kernel<<<blocks, TPB, SMEM_BYTES>>>(tokens, tokE, posE, W1, W2, Wout,
                                           out);
}

// round 8
// speedup vs baseline: 1.8225x; 1.0684x over previous
#include <cuda_runtime.h>
#include <cstdint>

#define TPB 128
#define RPB 256   // rows per block (2 per thread)

// ---------------- precomputed tables (device globals; no allocation) --------
__device__ float g_Qtab[216 * 32];
__device__ float g_Ktab[216 * 32];
__device__ float g_Vtab[216 * 32];
__device__ float g_Etab[216 * 216];   // exp(score): [(tok_t*8+t)*216 + tok_s*8+s]

// ---------------- packed f32x2 helpers ----------------
__device__ __forceinline__ unsigned long long fma2(unsigned long long a,
                                                   unsigned long long b,
                                                   unsigned long long c) {
    unsigned long long d;
    asm("fma.rn.f32x2 %0, %1, %2, %3;" : "=l"(d) : "l"(a), "l"(b), "l"(c));
    return d;
}
__device__ __forceinline__ unsigned long long pack2(float lo, float hi) {
    unsigned long long r;
    asm("mov.b64 %0, {%1, %2};" : "=l"(r) : "f"(lo), "f"(hi));
    return r;
}
__device__ __forceinline__ void unpack2(float& lo, float& hi, unsigned long long v) {
    asm("mov.b64 {%0, %1}, %2;" : "=f"(lo), "=f"(hi) : "l"(v));
}

// ---------------- pre-kernel 1: QKV tables (216 blocks x 96 threads) --------
__global__ void qkv_tab_kernel(const float* __restrict__ tokE,
                               const float* __restrict__ posE,
                               const float* __restrict__ Wq,
                               const float* __restrict__ Wk,
                               const float* __restrict__ Wv) {
    const int r   = blockIdx.x;          // 0..215
    const int tok = r >> 3, t = r & 7;
    const int mat = threadIdx.x >> 5;    // 0..2
    const int n   = threadIdx.x & 31;
    const float* W = (mat == 0) ? Wq : (mat == 1) ? Wk : Wv;
    float* T = (mat == 0) ? g_Qtab : (mat == 1) ? g_Ktab : g_Vtab;
    float acc = 0.f;
#pragma unroll
    for (int d = 0; d < 32; d++)
        acc += (tokE[tok * 32 + d] + posE[t * 32 + d]) * W[d * 32 + n];
    T[r * 32 + n] = acc;
}

// ---------------- pre-kernel 2: exp(score) table (216 x 216) ----------------
__global__ void stab_kernel() {
    int e = blockIdx.x * blockDim.x + threadIdx.x;
    if (e >= 216 * 216) return;
    int rq = e / 216, rk = e - rq * 216;
    const float* Q = g_Qtab + rq * 32;
    const float* K = g_Ktab + rk * 32;
    float s = 0.f;
#pragma unroll
    for (int d = 0; d < 32; d++) s += Q[d] * K[d];
    g_Etab[e] = __expf(s);   // scores are O(1e-4): exp without max is safe
}

// ---------------- main kernel smem layout (floats) ----------------
static constexpr int OFF_W1   = 0;      // 32 x 64
static constexpr int OFF_W2   = 2048;   // 64 x 32
static constexpr int OFF_WOUT = 4096;   // 32 x 28 padded
static constexpr int OFF_TOKE = 4992;   // 27 x 36
static constexpr int OFF_POSE = 5964;   // 8 x 36
static constexpr int OFF_VT   = 6252;   // 216 x 36  (V table; reused for out)
static constexpr int SMEM_FLOATS = 14028;
static constexpr int SMEM_BYTES  = SMEM_FLOATS * 4;   // 56112 B

extern __shared__ float sm[];

__device__ __forceinline__ void layernorm32(float* v) {
    float s1 = 0.0f, s2 = 0.0f;
#pragma unroll
    for (int e = 0; e < 32; e++) { s1 += v[e]; s2 += v[e] * v[e]; }
    float mu  = s1 * (1.0f / 32.0f);
    float var = s2 * (1.0f / 32.0f) - mu * mu;
    float rs  = rsqrtf(var + 1e-5f);
#pragma unroll
    for (int e = 0; e < 32; e++) v[e] = (v[e] - mu) * rs;
}

__global__ void __launch_bounds__(TPB, 3)
mt_kernel(const int* __restrict__ tokens,
          const float* __restrict__ g_tokE, const float* __restrict__ g_posE,
          const float* __restrict__ g_W1,  const float* __restrict__ g_W2,
          const float* __restrict__ g_Wout,
          float* __restrict__ g_out)
{
    float* s_W1   = sm + OFF_W1;
    float* s_W2   = sm + OFF_W2;
    float* s_Wout = sm + OFF_WOUT;
    float* s_tokE = sm + OFF_TOKE;
    float* s_posE = sm + OFF_POSE;
    float* s_VT   = sm + OFF_VT;

    const int tid = threadIdx.x;
    const int t   = tid & 7;

    // ---- EARLY: token loads + score-table gathers (latency hides under
    //      the staging stores below) ----
    const int r0 = blockIdx.x * RPB + tid;
    const int b0 = r0 >> 3;
    const int b1 = b0 + 16;
    const int4 ta0 = *(const int4*)(tokens + b0 * 8);
    const int4 tb0 = *(const int4*)(tokens + b0 * 8 + 4);
    const int4 ta1 = *(const int4*)(tokens + b1 * 8);
    const int4 tb1 = *(const int4*)(tokens + b1 * 8 + 4);
    const int tk0[8] = {ta0.x, ta0.y, ta0.z, ta0.w, tb0.x, tb0.y, tb0.z, tb0.w};
    const int tk1[8] = {ta1.x, ta1.y, ta1.z, ta1.w, tb1.x, tb1.y, tb1.z, tb1.w};
    const int tok0 = tk0[t] & 31;
    const int tok1 = tk1[t] & 31;

    const int sb0 = (tok0 * 8 + t) * 216;
    const int sb1 = (tok1 * 8 + t) * 216;
    float p0[8], p1[8];   // exp(score) gathers, then probabilities in-place
#pragma unroll
    for (int s = 0; s < 8; s++) {
        p0[s] = __ldg(g_Etab + sb0 + tk0[s] * 8 + s);
        p1[s] = __ldg(g_Etab + sb1 + tk1[s] * 8 + s);
    }

    // ---- cooperative staging ----
#pragma unroll
    for (int b = 0; b < 2048; b += TPB * 4) {
        int i = b + tid * 4;
        *(float4*)(s_W1 + i) = *(const float4*)(g_W1 + i);
        *(float4*)(s_W2 + i) = *(const float4*)(g_W2 + i);
    }
    for (int i = tid; i < 32 * 28; i += TPB) {
        int e = i / 28, c = i % 28;
        s_Wout[i] = (c < 27) ? g_Wout[e * 27 + c] : 0.0f;
    }
    for (int i = tid; i < 27 * 32; i += TPB) {
        int r = i >> 5, c = i & 31;
        s_tokE[r * 36 + c] = g_tokE[i];
    }
    for (int i = tid; i < 8 * 32; i += TPB) {
        int r = i >> 5, c = i & 31;
        s_posE[r * 36 + c] = g_posE[i];
    }
    for (int i = tid; i < 216 * 8; i += TPB) {   // V table, stride-36 padded
        int r = i >> 3, c = i & 7;
        *(float4*)(s_VT + r * 36 + c * 4) = *(const float4*)(g_Vtab + r * 32 + c * 4);
    }
    __syncthreads();

    // ---- softmax weights (causal: s <= t); exp already in table ----
    float sum0 = 0.0f, sum1 = 0.0f;
#pragma unroll
    for (int s = 0; s < 8; s++) {
        p0[s] = (s <= t) ? p0[s] : 0.0f;
        p1[s] = (s <= t) ? p1[s] : 0.0f;
        sum0 += p0[s]; sum1 += p1[s];
    }
    const float inv0 = 1.0f / sum0;
    const float inv1 = 1.0f / sum1;

    // ---- out = attn @ V (V rows from smem table) ----
    unsigned long long o0[16], o1[16];
#pragma unroll
    for (int i = 0; i < 16; i++) { o0[i] = 0ULL; o1[i] = 0ULL; }
#pragma unroll
    for (int s = 0; s < 8; s++) {
        float a = p0[s] * inv0;
        float b = p1[s] * inv1;
        unsigned long long aa = pack2(a, a);
        unsigned long long bb = pack2(b, b);
        const ulonglong2* va = (const ulonglong2*)(s_VT + (tk0[s] * 8 + s) * 36);
        const ulonglong2* vb = (const ulonglong2*)(s_VT + (tk1[s] * 8 + s) * 36);
#pragma unroll
        for (int i = 0; i < 8; i++) {
            ulonglong2 wa = va[i], wb = vb[i];
            o0[2 * i]     = fma2(aa, wa.x, o0[2 * i]);
            o0[2 * i + 1] = fma2(aa, wa.y, o0[2 * i + 1]);
            o1[2 * i]     = fma2(bb, wb.x, o1[2 * i]);
            o1[2 * i + 1] = fma2(bb, wb.y, o1[2 * i + 1]);
        }
    }

    // ---- LN1(out + x), x rebuilt from tokE/posE smem ----
    float n1a[32], n1b[32];
#pragma unroll
    for (int i = 0; i < 8; i++) {
        float4 pp = *(const float4*)(s_posE + t * 36 + i * 4);
        float4 xa = *(const float4*)(s_tokE + tok0 * 36 + i * 4);
        float4 xb = *(const float4*)(s_tokE + tok1 * 36 + i * 4);
        float lo, hi;
        unpack2(lo, hi, o0[2 * i]);
        n1a[4 * i + 0] = lo + xa.x + pp.x;
        n1a[4 * i + 1] = hi + xa.y + pp.y;
        unpack2(lo, hi, o0[2 * i + 1]);
        n1a[4 * i + 2] = lo + xa.z + pp.z;
        n1a[4 * i + 3] = hi + xa.w + pp.w;
        unpack2(lo, hi, o1[2 * i]);
        n1b[4 * i + 0] = lo + xb.x + pp.x;
        n1b[4 * i + 1] = hi + xb.y + pp.y;
        unpack2(lo, hi, o1[2 * i + 1]);
        n1b[4 * i + 2] = lo + xb.z + pp.z;
        n1b[4 * i + 3] = hi + xb.w + pp.w;
    }
    layernorm32(n1a);
    layernorm32(n1b);

    // ---- MLP: relu(n1 @ W1) @ W2, h in 8 chunks of 8 ----
    unsigned long long y0[16], y1[16];
#pragma unroll
    for (int i = 0; i < 16; i++) { y0[i] = 0ULL; y1[i] = 0ULL; }
#pragma unroll 1
    for (int c = 0; c < 8; c++) {
        unsigned long long h0[4], h1[4];
#pragma unroll
        for (int i = 0; i < 4; i++) { h0[i] = 0ULL; h1[i] = 0ULL; }
#pragma unroll
        for (int e = 0; e < 32; e++) {
            unsigned long long b0v = pack2(n1a[e], n1a[e]);
            unsigned long long b1v = pack2(n1b[e], n1b[e]);
            const ulonglong2* w = (const ulonglong2*)(s_W1 + e * 64 + c * 8);
#pragma unroll
            for (int i = 0; i < 2; i++) {
                ulonglong2 ww = w[i];
                h0[2 * i]     = fma2(b0v, ww.x, h0[2 * i]);
                h0[2 * i + 1] = fma2(b0v, ww.y, h0[2 * i + 1]);
                h1[2 * i]     = fma2(b1v, ww.x, h1[2 * i]);
                h1[2 * i + 1] = fma2(b1v, ww.y, h1[2 * i + 1]);
            }
        }
#pragma unroll
        for (int j = 0; j < 4; j++) {
            float ha0, ha1, hb0, hb1;
            unpack2(ha0, ha1, h0[j]);
            unpack2(hb0, hb1, h1[j]);
            ha0 = fmaxf(ha0, 0.0f); ha1 = fmaxf(ha1, 0.0f);
            hb0 = fmaxf(hb0, 0.0f); hb1 = fmaxf(hb1, 0.0f);
            const ulonglong2* wa =
                (const ulonglong2*)(s_W2 + (c * 8 + 2 * j) * 32);
            {
                unsigned long long pa = pack2(ha0, ha0);
                unsigned long long pb = pack2(hb0, hb0);
#pragma unroll
                for (int i = 0; i < 8; i++) {
                    ulonglong2 ww = wa[i];
                    y0[2 * i]     = fma2(pa, ww.x, y0[2 * i]);
                    y0[2 * i + 1] = fma2(pa, ww.y, y0[2 * i + 1]);
                    y1[2 * i]     = fma2(pb, ww.x, y1[2 * i]);
                    y1[2 * i + 1] = fma2(pb, ww.y, y1[2 * i + 1]);
                }
            }
            {
                unsigned long long pa = pack2(ha1, ha1);
                unsigned long long pb = pack2(hb1, hb1);
                const ulonglong2* wb = wa + 8;
#pragma unroll
                for (int i = 0; i < 8; i++) {
                    ulonglong2 ww = wb[i];
                    y0[2 * i]     = fma2(pa, ww.x, y0[2 * i]);
                    y0[2 * i + 1] = fma2(pa, ww.y, y0[2 * i + 1]);
                    y1[2 * i]     = fma2(pb, ww.x, y1[2 * i]);
                    y1[2 * i + 1] = fma2(pb, ww.y, y1[2 * i + 1]);
                }
            }
        }
    }

    // ---- LN2(y + n1) ----
    float n2a[32], n2b[32];
#pragma unroll
    for (int i = 0; i < 16; i++) {
        float lo, hi;
        unpack2(lo, hi, y0[i]);
        n2a[2 * i] = lo + n1a[2 * i];  n2a[2 * i + 1] = hi + n1a[2 * i + 1];
        unpack2(lo, hi, y1[i]);
        n2b[2 * i] = lo + n1b[2 * i];  n2b[2 * i + 1] = hi + n1b[2 * i + 1];
    }
    layernorm32(n2a);
    layernorm32(n2b);

    // ---- logits = n2 @ Wout (28-padded; col 27 is zero) ----
    unsigned long long l0[14], l1[14];
#pragma unroll
    for (int i = 0; i < 14; i++) { l0[i] = 0ULL; l1[i] = 0ULL; }
#pragma unroll
    for (int e = 0; e < 32; e++) {
        unsigned long long b0v = pack2(n2a[e], n2a[e]);
        unsigned long long b1v = pack2(n2b[e], n2b[e]);
        const ulonglong2* w = (const ulonglong2*)(s_Wout + e * 28);
#pragma unroll
        for (int i = 0; i < 7; i++) {
            ulonglong2 ww = w[i];
            l0[2 * i]     = fma2(b0v, ww.x, l0[2 * i]);
            l0[2 * i + 1] = fma2(b0v, ww.y, l0[2 * i + 1]);
            l1[2 * i]     = fma2(b1v, ww.x, l1[2 * i]);
            l1[2 * i + 1] = fma2(b1v, ww.y, l1[2 * i + 1]);
        }
    }

    // ---- stage outputs in smem (reuse V-table region), coalesced STG ----
    __syncthreads();   // all threads done reading the V table
    float* s_out = s_VT;   // 256*27 = 6912 floats <= 7776
    {
        float* oa = s_out + tid * 27;
        float* ob = s_out + (TPB + tid) * 27;
#pragma unroll
        for (int i = 0; i < 13; i++) {
            float lo, hi;
            unpack2(lo, hi, l0[i]); oa[2 * i] = lo; oa[2 * i + 1] = hi;
            unpack2(lo, hi, l1[i]); ob[2 * i] = lo; ob[2 * i + 1] = hi;
        }
        float lo, hi;
        unpack2(lo, hi, l0[13]); oa[26] = lo;
        unpack2(lo, hi, l1[13]); ob[26] = lo;
    }
    __syncthreads();
    {
        const float4* src = (const float4*)s_out;
        float4* dst = (float4*)(g_out + (size_t)blockIdx.x * RPB * 27);
#pragma unroll
        for (int b = 0; b < 1728; b += TPB) {
            int i = b + tid;
            if (i < 1728) dst[i] = src[i];
        }
    }
}

extern "C" void kernel_launch(void* const* d_in, const int* in_sizes, int n_in,
                              void* d_out, int out_size) {
    const int*   tokens = (const int*)d_in[0];
    const float* tokE   = (const float*)d_in[1];
    const float* posE   = (const float*)d_in[2];
    const float* Wq     = (const float*)d_in[3];
    const float* Wk     = (const float*)d_in[4];
    const float* Wv     = (const float*)d_in[5];
    const float* W1     = (const float*)d_in[6];
    const float* W2     = (const float*)d_in[7];
    const float* Wout   = (const float*)d_in[8];
    float*       out    = (float*)d_out;

    cudaFuncSetAttribute(mt_kernel, cudaFuncAttributeMaxDynamicSharedMemorySize,
                         SMEM_BYTES);

    // parallel table precompute, then the fused main kernel — same stream
    qkv_tab_kernel<<<216, 96>>>(tokE, posE, Wq, Wk, Wv);
    stab_kernel<<<(216 * 216 + 255) / 256, 256>>>();

    const int rows   = in_sizes[0];   // B*T = 1048576
    const int blocks = rows / RPB;    // 4096
    mt_kernel<<<blocks, TPB, SMEM_BYTES>>>(tokens, tokE, posE, W1, W2, Wout,
                                           out);
}